// round 1
// baseline (speedup 1.0000x reference)
#include <cuda_runtime.h>
#include <cuda_bf16.h>
#include <math.h>

// Problem constants
#define BB 4
#define SS 2048
#define DD 768
#define UU 768

// Scratch (allocations are forbidden; static __device__ arrays are the sanctioned escape hatch)
__device__ float g_Q[BB * SS * UU];      // 25 MB
__device__ float g_K[BB * SS * UU];      // 25 MB
__device__ float g_V[BB * SS * UU];      // 25 MB
__device__ float g_Sc[(size_t)BB * SS * SS]; // 67 MB

// ---------------------------------------------------------------------------
// 128x128x16 fp32 tiled GEMM, 256 threads, 8x8 register tile per thread.
//   C[M,N] = alpha * A[M,K] * op(B)
//   BTRANS=false: B is [K,N] row-major.  BTRANS=true: B is [N,K] row-major (C=A*B^T).
// All of M, N divisible by 128; K divisible by 16 (true for all calls here).
// Batched over blockIdx.z with element strides sA/sB/sC.
// ---------------------------------------------------------------------------
template <bool BTRANS>
__global__ __launch_bounds__(256) void gemm128(
    const float* __restrict__ A, const float* __restrict__ B,
    float* __restrict__ C, int M, int N, int K,
    long sA, long sB, long sC, float alpha)
{
    __shared__ float As[16][132];  // k-major, padded
    __shared__ float Bs[16][132];  // k-major, padded

    A += (long)blockIdx.z * sA;
    B += (long)blockIdx.z * sB;
    C += (long)blockIdx.z * sC;

    const int row0 = blockIdx.y * 128;
    const int col0 = blockIdx.x * 128;
    const int tid = threadIdx.x;
    const int tx = tid & 15;
    const int ty = tid >> 4;

    float acc[8][8];
#pragma unroll
    for (int i = 0; i < 8; i++)
#pragma unroll
        for (int j = 0; j < 8; j++) acc[i][j] = 0.f;

    for (int k0 = 0; k0 < K; k0 += 16) {
        // --- load A tile: 128 rows x 16 k, scattered into k-major smem ---
#pragma unroll
        for (int l = 0; l < 2; l++) {
            int idx = tid + l * 256;        // 0..511
            int r   = idx >> 2;             // 0..127
            int ks  = (idx & 3) * 4;        // 0,4,8,12
            float4 v = *(const float4*)(A + (long)(row0 + r) * K + k0 + ks);
            As[ks + 0][r] = v.x; As[ks + 1][r] = v.y;
            As[ks + 2][r] = v.z; As[ks + 3][r] = v.w;
        }
        // --- load B tile ---
        if (BTRANS) {
#pragma unroll
            for (int l = 0; l < 2; l++) {
                int idx = tid + l * 256;
                int c   = idx >> 2;
                int ks  = (idx & 3) * 4;
                float4 v = *(const float4*)(B + (long)(col0 + c) * K + k0 + ks);
                Bs[ks + 0][c] = v.x; Bs[ks + 1][c] = v.y;
                Bs[ks + 2][c] = v.z; Bs[ks + 3][c] = v.w;
            }
        } else {
#pragma unroll
            for (int l = 0; l < 2; l++) {
                int idx = tid + l * 256;
                int kk  = idx >> 5;          // 0..15
                int cs  = (idx & 31) * 4;    // 0..124
                float4 v = *(const float4*)(B + (long)(k0 + kk) * N + col0 + cs);
                *(float4*)&Bs[kk][cs] = v;
            }
        }
        __syncthreads();

#pragma unroll
        for (int kk = 0; kk < 16; kk++) {
            float a[8], b[8];
            float4 a0 = *(const float4*)&As[kk][ty * 4];
            float4 a1 = *(const float4*)&As[kk][ty * 4 + 64];
            float4 b0 = *(const float4*)&Bs[kk][tx * 4];
            float4 b1 = *(const float4*)&Bs[kk][tx * 4 + 64];
            a[0] = a0.x; a[1] = a0.y; a[2] = a0.z; a[3] = a0.w;
            a[4] = a1.x; a[5] = a1.y; a[6] = a1.z; a[7] = a1.w;
            b[0] = b0.x; b[1] = b0.y; b[2] = b0.z; b[3] = b0.w;
            b[4] = b1.x; b[5] = b1.y; b[6] = b1.z; b[7] = b1.w;
#pragma unroll
            for (int i = 0; i < 8; i++)
#pragma unroll
                for (int j = 0; j < 8; j++)
                    acc[i][j] = fmaf(a[i], b[j], acc[i][j]);
        }
        __syncthreads();
    }

    // --- epilogue ---
#pragma unroll
    for (int i = 0; i < 8; i++) {
        int r = row0 + ((i < 4) ? (ty * 4 + i) : (64 + ty * 4 + i - 4));
        float4 o0 = make_float4(acc[i][0] * alpha, acc[i][1] * alpha,
                                acc[i][2] * alpha, acc[i][3] * alpha);
        float4 o1 = make_float4(acc[i][4] * alpha, acc[i][5] * alpha,
                                acc[i][6] * alpha, acc[i][7] * alpha);
        *(float4*)(C + (long)r * N + col0 + tx * 4)      = o0;
        *(float4*)(C + (long)r * N + col0 + tx * 4 + 64) = o1;
    }
}

// ---------------------------------------------------------------------------
// Row softmax over S=2048 columns. One block (256 threads) per row.
// ---------------------------------------------------------------------------
__global__ __launch_bounds__(256) void softmax_rows(float* __restrict__ scores)
{
    float* row = scores + (long)blockIdx.x * SS;
    __shared__ float red[256];
    const int t = threadIdx.x;

    float v[8];
    float m = -INFINITY;
#pragma unroll
    for (int i = 0; i < 8; i++) {
        v[i] = row[t + i * 256];
        m = fmaxf(m, v[i]);
    }
    red[t] = m;
    __syncthreads();
    for (int s = 128; s > 0; s >>= 1) {
        if (t < s) red[t] = fmaxf(red[t], red[t + s]);
        __syncthreads();
    }
    m = red[0];
    __syncthreads();

    float sum = 0.f;
#pragma unroll
    for (int i = 0; i < 8; i++) {
        v[i] = expf(v[i] - m);
        sum += v[i];
    }
    red[t] = sum;
    __syncthreads();
    for (int s = 128; s > 0; s >>= 1) {
        if (t < s) red[t] += red[t + s];
        __syncthreads();
    }
    float inv = 1.f / red[0];
#pragma unroll
    for (int i = 0; i < 8; i++)
        row[t + i * 256] = v[i] * inv;
}

// ---------------------------------------------------------------------------
extern "C" void kernel_launch(void* const* d_in, const int* in_sizes, int n_in,
                              void* d_out, int out_size)
{
    (void)in_sizes; (void)n_in; (void)out_size;
    const float* x  = (const float*)d_in[0];
    const float* Wq = (const float*)d_in[1];
    const float* Wk = (const float*)d_in[2];
    const float* Wv = (const float*)d_in[3];
    float* out = (float*)d_out;

    float *Q, *K, *V, *Sc;
    cudaGetSymbolAddress((void**)&Q,  g_Q);
    cudaGetSymbolAddress((void**)&K,  g_K);
    cudaGetSymbolAddress((void**)&V,  g_V);
    cudaGetSymbolAddress((void**)&Sc, g_Sc);

    const int M = BB * SS;               // 8192
    const float scale = 1.f / sqrtf((float)UU);

    // 1) QKV projections: [8192,768] x [768,768]
    dim3 gp(UU / 128, M / 128, 1);       // (6, 64, 1)
    gemm128<false><<<gp, 256>>>(x, Wq, Q, M, UU, DD, 0, 0, 0, 1.f);
    gemm128<false><<<gp, 256>>>(x, Wk, K, M, UU, DD, 0, 0, 0, 1.f);
    gemm128<false><<<gp, 256>>>(x, Wv, V, M, UU, DD, 0, 0, 0, 1.f);

    // 2) scores = scale * Q @ K^T, batched over B
    dim3 gs(SS / 128, SS / 128, BB);     // (16, 16, 4)
    gemm128<true><<<gs, 256>>>(Q, K, Sc, SS, SS, UU,
                               (long)SS * UU, (long)SS * UU, (long)SS * SS, scale);

    // 3) softmax rows
    softmax_rows<<<BB * SS, 256>>>(Sc);

    // 4) out = attn @ V, batched over B
    dim3 ga(UU / 128, SS / 128, BB);     // (6, 16, 4)
    gemm128<false><<<ga, 256>>>(Sc, V, out, SS, UU, SS,
                                (long)SS * SS, (long)SS * UU, (long)SS * UU, 1.f);
}

// round 4
// speedup vs baseline: 2.6446x; 2.6446x over previous
#include <cuda_runtime.h>
#include <cuda_bf16.h>
#include <cstdint>
#include <math.h>

#define BB 4
#define SS 2048
#define DD 768
#define UU 768

// ---------------- scratch (static __device__; allocs forbidden) --------------
__device__ float g_Q[BB * SS * UU];
__device__ float g_K[BB * SS * UU];
__device__ float g_V[BB * SS * UU];
__device__ float g_Vt[BB * UU * SS];
__device__ float g_Sc[(size_t)BB * SS * SS];
__device__ float g_Wqt[DD * UU];
__device__ float g_Wkt[DD * UU];
__device__ float g_Wvt[DD * UU];

// ---------------- helpers ----------------------------------------------------
__device__ __forceinline__ void cp16(uint32_t s, const void* g) {
    asm volatile("cp.async.cg.shared.global [%0], [%1], 16;\n" :: "r"(s), "l"(g) : "memory");
}
__device__ __forceinline__ void cp_commit() {
    asm volatile("cp.async.commit_group;\n" ::: "memory");
}
template <int N>
__device__ __forceinline__ void cp_wait() {
    asm volatile("cp.async.wait_group %0;\n" :: "n"(N) : "memory");
}
__device__ __forceinline__ uint32_t f2tf32(float f) {
    uint32_t o;
    asm("cvt.rna.tf32.f32 %0, %1;" : "=r"(o) : "f"(f));
    return o;
}
__device__ __forceinline__ void mma_tf32(float* d, const uint32_t* a, const uint32_t* b) {
    asm volatile("mma.sync.aligned.m16n8k8.row.col.f32.tf32.tf32.f32 "
                 "{%0,%1,%2,%3}, {%4,%5,%6,%7}, {%8,%9}, {%0,%1,%2,%3};"
                 : "+f"(d[0]), "+f"(d[1]), "+f"(d[2]), "+f"(d[3])
                 : "r"(a[0]), "r"(a[1]), "r"(a[2]), "r"(a[3]), "r"(b[0]), "r"(b[1]));
}

// ---------------- tf32 warp-MMA GEMM: C[M,N] = alpha * A[M,K] * B[N,K]^T -----
// CTA tile 128x128, K-chunk 16, 8 warps (2 M x 4 N), warp tile 64x32.
// Smem: [row][k] with stride 20 floats (conflict-free fragment loads).
#define STRD 20

__global__ __launch_bounds__(256, 2) void gemm_mma(
    const float* __restrict__ A, const float* __restrict__ B, float* __restrict__ C,
    int M, int N, int K, long sA, long sB, long sC, float alpha)
{
    __shared__ float As[2][128][STRD];
    __shared__ float Bs[2][128][STRD];

    A += (long)blockIdx.z * sA;
    B += (long)blockIdx.z * sB;
    C += (long)blockIdx.z * sC;

    const int row0 = blockIdx.y * 128;
    const int col0 = blockIdx.x * 128;
    const int tid  = threadIdx.x;
    const int wid  = tid >> 5;
    const int lane = tid & 31;
    const int g    = lane >> 2;        // group id (0..7)
    const int t    = lane & 3;         // thread-in-group (0..3)
    const int wm   = wid & 1;          // warp m index (0..1)
    const int wn   = wid >> 1;         // warp n index (0..3)

    const uint32_t sA0 = (uint32_t)__cvta_generic_to_shared(&As[0][0][0]);
    const uint32_t sB0 = (uint32_t)__cvta_generic_to_shared(&Bs[0][0][0]);

    float acc[4][4][4];
#pragma unroll
    for (int i = 0; i < 4; i++)
#pragma unroll
        for (int j = 0; j < 4; j++)
#pragma unroll
            for (int r = 0; r < 4; r++) acc[i][j][r] = 0.f;

    const int KT = K / 16;

    // prologue: load chunk 0 into buf 0
    {
        const int m  = tid >> 1;             // 0..127  (2 chunks of 4k per row)
        const int kc = (tid & 1) * 2;        // 0 or 2 → covers kc 0..3 via 2 cp16 each? no:
        // 512 cp16 per tile: do it as two passes of 256
#pragma unroll
        for (int i = 0; i < 2; i++) {
            int idx = tid + i * 256;         // 0..511
            int r   = idx >> 2;              // row 0..127
            int c   = idx & 3;               // k-chunk 0..3
            cp16(sA0 + (uint32_t)((r * STRD + c * 4) * 4),
                 A + (long)(row0 + r) * K + c * 4);
            cp16(sB0 + (uint32_t)((r * STRD + c * 4) * 4),
                 B + (long)(col0 + r) * K + c * 4);
        }
        cp_commit();
        (void)m; (void)kc;
    }

    for (int kt = 0; kt < KT; kt++) {
        const int buf = kt & 1;
        // prefetch next chunk into buf^1
        if (kt + 1 < KT) {
            const uint32_t dA = sA0 + (uint32_t)((buf ^ 1) * 128 * STRD * 4);
            const uint32_t dB = sB0 + (uint32_t)((buf ^ 1) * 128 * STRD * 4);
            const int k0 = (kt + 1) * 16;
#pragma unroll
            for (int i = 0; i < 2; i++) {
                int idx = tid + i * 256;
                int r   = idx >> 2;
                int c   = idx & 3;
                cp16(dA + (uint32_t)((r * STRD + c * 4) * 4),
                     A + (long)(row0 + r) * K + k0 + c * 4);
                cp16(dB + (uint32_t)((r * STRD + c * 4) * 4),
                     B + (long)(col0 + r) * K + k0 + c * 4);
            }
            cp_commit();
            cp_wait<1>();
        } else {
            cp_wait<0>();
        }
        __syncthreads();

        // compute chunk kt
#pragma unroll
        for (int ks = 0; ks < 2; ks++) {
            const int kb = ks * 8;
            uint32_t af[4][4], bf[4][2];
#pragma unroll
            for (int mi = 0; mi < 4; mi++) {
                const int m0 = wm * 64 + mi * 16;
                af[mi][0] = f2tf32(As[buf][m0 + g][kb + t]);
                af[mi][1] = f2tf32(As[buf][m0 + g + 8][kb + t]);
                af[mi][2] = f2tf32(As[buf][m0 + g][kb + t + 4]);
                af[mi][3] = f2tf32(As[buf][m0 + g + 8][kb + t + 4]);
            }
#pragma unroll
            for (int ni = 0; ni < 4; ni++) {
                const int n0 = wn * 32 + ni * 8;
                bf[ni][0] = f2tf32(Bs[buf][n0 + g][kb + t]);
                bf[ni][1] = f2tf32(Bs[buf][n0 + g][kb + t + 4]);
            }
#pragma unroll
            for (int mi = 0; mi < 4; mi++)
#pragma unroll
                for (int ni = 0; ni < 4; ni++)
                    mma_tf32(acc[mi][ni], af[mi], bf[ni]);
        }
        __syncthreads();
    }

    // epilogue
#pragma unroll
    for (int mi = 0; mi < 4; mi++) {
        const int r0 = row0 + wm * 64 + mi * 16 + g;
#pragma unroll
        for (int ni = 0; ni < 4; ni++) {
            const int c = col0 + wn * 32 + ni * 8 + 2 * t;
            float2 v0 = make_float2(acc[mi][ni][0] * alpha, acc[mi][ni][1] * alpha);
            float2 v1 = make_float2(acc[mi][ni][2] * alpha, acc[mi][ni][3] * alpha);
            *(float2*)(C + (long)r0 * N + c)       = v0;
            *(float2*)(C + (long)(r0 + 8) * N + c) = v1;
        }
    }
}

// ---------------- transpose: out[b][c][r] = in[b][r][c] ----------------------
__global__ __launch_bounds__(256) void transpose32(
    const float* __restrict__ in, float* __restrict__ out,
    int R, int C, long sIn, long sOut)
{
    __shared__ float tbuf[32][33];
    in  += (long)blockIdx.z * sIn;
    out += (long)blockIdx.z * sOut;
    const int c0 = blockIdx.x * 32, r0 = blockIdx.y * 32;
    const int tx = threadIdx.x & 31, ty = threadIdx.x >> 5;  // 32x8
#pragma unroll
    for (int i = 0; i < 32; i += 8)
        tbuf[ty + i][tx] = in[(long)(r0 + ty + i) * C + c0 + tx];
    __syncthreads();
#pragma unroll
    for (int i = 0; i < 32; i += 8)
        out[(long)(c0 + ty + i) * R + r0 + tx] = tbuf[tx][ty + i];
}

// ---------------- row softmax over S=2048 ------------------------------------
__global__ __launch_bounds__(256) void softmax_rows(float* __restrict__ scores)
{
    float* row = scores + (long)blockIdx.x * SS;
    __shared__ float red[256];
    const int t = threadIdx.x;
    float v[8];
    float m = -INFINITY;
#pragma unroll
    for (int i = 0; i < 8; i++) { v[i] = row[t + i * 256]; m = fmaxf(m, v[i]); }
    red[t] = m; __syncthreads();
    for (int s = 128; s > 0; s >>= 1) { if (t < s) red[t] = fmaxf(red[t], red[t + s]); __syncthreads(); }
    m = red[0]; __syncthreads();
    float sum = 0.f;
#pragma unroll
    for (int i = 0; i < 8; i++) { v[i] = expf(v[i] - m); sum += v[i]; }
    red[t] = sum; __syncthreads();
    for (int s = 128; s > 0; s >>= 1) { if (t < s) red[t] += red[t + s]; __syncthreads(); }
    float inv = 1.f / red[0];
#pragma unroll
    for (int i = 0; i < 8; i++) row[t + i * 256] = v[i] * inv;
}

// ---------------------------------------------------------------------------
extern "C" void kernel_launch(void* const* d_in, const int* in_sizes, int n_in,
                              void* d_out, int out_size)
{
    (void)in_sizes; (void)n_in; (void)out_size;
    const float* x  = (const float*)d_in[0];
    const float* Wq = (const float*)d_in[1];
    const float* Wk = (const float*)d_in[2];
    const float* Wv = (const float*)d_in[3];
    float* out = (float*)d_out;

    float *Q, *K, *V, *Vt, *Sc, *Wqt, *Wkt, *Wvt;
    cudaGetSymbolAddress((void**)&Q,   g_Q);
    cudaGetSymbolAddress((void**)&K,   g_K);
    cudaGetSymbolAddress((void**)&V,   g_V);
    cudaGetSymbolAddress((void**)&Vt,  g_Vt);
    cudaGetSymbolAddress((void**)&Sc,  g_Sc);
    cudaGetSymbolAddress((void**)&Wqt, g_Wqt);
    cudaGetSymbolAddress((void**)&Wkt, g_Wkt);
    cudaGetSymbolAddress((void**)&Wvt, g_Wvt);

    const int M = BB * SS;                       // 8192
    const float scale = 1.f / sqrtf((float)UU);

    // 0) transpose weights [D,U] -> [U,D]  (square 768x768)
    dim3 tw(DD / 32, UU / 32, 1);
    transpose32<<<tw, 256>>>(Wq, Wqt, DD, UU, 0, 0);
    transpose32<<<tw, 256>>>(Wk, Wkt, DD, UU, 0, 0);
    transpose32<<<tw, 256>>>(Wv, Wvt, DD, UU, 0, 0);

    // 1) QKV projections: Q = x @ W == A[M,768] * (W^T)[768,768]^T
    dim3 gp(UU / 128, M / 128, 1);               // (6, 64)
    gemm_mma<<<gp, 256>>>(x, Wqt, Q, M, UU, DD, 0, 0, 0, 1.f);
    gemm_mma<<<gp, 256>>>(x, Wkt, K, M, UU, DD, 0, 0, 0, 1.f);
    gemm_mma<<<gp, 256>>>(x, Wvt, V, M, UU, DD, 0, 0, 0, 1.f);

    // 1b) transpose V per batch: [S,U] -> [U,S]
    dim3 tv(UU / 32, SS / 32, BB);
    transpose32<<<tv, 256>>>(V, Vt, SS, UU, (long)SS * UU, (long)SS * UU);

    // 2) scores = scale * Q @ K^T (batched)
    dim3 gs(SS / 128, SS / 128, BB);             // (16, 16, 4)
    gemm_mma<<<gs, 256>>>(Q, K, Sc, SS, SS, UU,
                          (long)SS * UU, (long)SS * UU, (long)SS * SS, scale);

    // 3) softmax rows
    softmax_rows<<<BB * SS, 256>>>(Sc);

    // 4) out = attn @ V == A[S,S] * (V^T)[U,S]^T (batched)
    dim3 ga(UU / 128, SS / 128, BB);             // (6, 16, 4)
    gemm_mma<<<ga, 256>>>(Sc, Vt, out, SS, UU, SS,
                          (long)SS * SS, (long)SS * UU, (long)SS * UU, 1.f);
}